// round 1
// baseline (speedup 1.0000x reference)
#include <cuda_runtime.h>

#define NW    32768
#define TMAX  16
#define CDIM  64
#define HID   256
#define G4    1024
#define WDIM  256
#define BW    16
#define NCTA  (NW / BW)

// Scratch (allocation-free rule: __device__ globals)
__device__ float d_G[256 * G4];          // gate table: G[v][g] = W_ih @ E_char[v] + b_ih + b_hh
__device__ float d_WhhT[HID * G4];       // W_hh transposed: [k][4H]
__device__ float d_WlinT[512 * WDIM];    // W_lin transposed: [k][256]
__device__ int   d_perm[NW];
__device__ int   d_cnt[16];
__device__ int   d_base[16];

__device__ __forceinline__ float sigf(float x) {
    return __fdividef(1.f, 1.f + __expf(-x));
}
__device__ __forceinline__ float tanhf_(float x) {
    x = fminf(fmaxf(x, -15.f), 15.f);
    float e = __expf(-2.f * x);
    return __fdividef(1.f - e, 1.f + e);
}

// ---------------- bucketing (counting sort by length, descending) ----------------
__global__ void k_zero() { if (threadIdx.x < 16) d_cnt[threadIdx.x] = 0; }

__global__ void k_hist(const int* __restrict__ lens) {
    int i = blockIdx.x * blockDim.x + threadIdx.x;
    if (i < NW) atomicAdd(&d_cnt[16 - lens[i]], 1);   // bucket 0 = len 16 (longest first)
}

__global__ void k_scan() {
    int s = 0;
    #pragma unroll
    for (int i = 0; i < 16; i++) { d_base[i] = s; s += d_cnt[i]; d_cnt[i] = 0; }
}

__global__ void k_scatter(const int* __restrict__ lens) {
    int i = blockIdx.x * blockDim.x + threadIdx.x;
    if (i < NW) {
        int b = 16 - lens[i];
        int pos = d_base[b] + atomicAdd(&d_cnt[b], 1);
        d_perm[pos] = i;
    }
}

// ---------------- weight prep ----------------
__global__ void k_prepG(const float* __restrict__ E, const float* __restrict__ Wih,
                        const float* __restrict__ bih, const float* __restrict__ bhh) {
    int gid = blockIdx.x * blockDim.x + threadIdx.x;   // 262144
    int v = gid >> 10, g = gid & 1023;
    float acc = bih[g] + bhh[g];
    const float* e = E + v * CDIM;
    const float* w = Wih + g * CDIM;
    #pragma unroll
    for (int k = 0; k < CDIM; k++) acc += e[k] * w[k];
    d_G[v * G4 + g] = acc;
}

__global__ void k_transWhh(const float* __restrict__ Whh) {
    int gid = blockIdx.x * blockDim.x + threadIdx.x;   // 262144
    int k = gid >> 10, g = gid & 1023;
    d_WhhT[gid] = Whh[g * HID + k];
}

__global__ void k_transWlin(const float* __restrict__ Wlin) {
    int gid = blockIdx.x * blockDim.x + threadIdx.x;   // 131072
    int k = gid >> 8, j = gid & 255;
    d_WlinT[gid] = Wlin[j * 512 + k];
}

// ---------------- main: fused LSTM + output linear ----------------
// CTA: 16 words, 256 threads. Thread t owns hidden unit t -> gates {t, t+256, t+512, t+768}.
// h lives in SMEM (broadcast reads across threads), c lives in registers (exclusively owned).
__global__ void __launch_bounds__(256, 2)
k_lstm(const int* __restrict__ chars, const int* __restrict__ lens,
       const float* __restrict__ wemb, const float* __restrict__ blin,
       float* __restrict__ out)
{
    __shared__ __align__(16) float h_s[BW][HID];
    __shared__ __align__(16) float x_s[BW][WDIM];
    __shared__ int word_s[BW];
    __shared__ int len_s[BW];
    __shared__ int ch_s[BW][TMAX];

    const int tid = threadIdx.x;

    if (tid < BW) {
        int w = d_perm[blockIdx.x * BW + tid];
        word_s[tid] = w;
        len_s[tid]  = lens[w];
    }
    __syncthreads();
    {
        int w = tid >> 4, t = tid & 15;
        ch_s[w][t] = chars[word_s[w] * TMAX + t];
    }
    #pragma unroll
    for (int w = 0; w < BW; w++)
        x_s[w][tid] = wemb[word_s[w] * WDIM + tid];
    __syncthreads();

    int maxlen = 1;
    #pragma unroll
    for (int w = 0; w < BW; w++) maxlen = max(maxlen, len_s[w]);

    float c[BW];

    // ---- t = 0: h0 = c0 = 0, so gates == G[char] (no GEMM) ----
    #pragma unroll
    for (int w = 0; w < BW; w++) {
        const float* g = d_G + ch_s[w][0] * G4 + tid;
        float gi = sigf(g[0]);
        float gf = sigf(g[256]); (void)gf;            // f*c0 = 0
        float gg = tanhf_(g[512]);
        float go = sigf(g[768]);
        c[w] = gi * gg;
        h_s[w][tid] = go * tanhf_(c[w]);
    }
    __syncthreads();

    // ---- t = 1 .. maxlen-1: gates = G[char] + W_hh @ h ----
    for (int t = 1; t < maxlen; t++) {
        float a0[BW], a1[BW], a2[BW], a3[BW];
        #pragma unroll
        for (int w = 0; w < BW; w++) {
            const float* g = d_G + ch_s[w][t] * G4 + tid;
            a0[w] = g[0]; a1[w] = g[256]; a2[w] = g[512]; a3[w] = g[768];
        }

        #pragma unroll 1
        for (int k = 0; k < HID; k += 4) {
            float wr[4][4];
            #pragma unroll
            for (int kk = 0; kk < 4; kk++) {
                const float* p = d_WhhT + (k + kk) * G4 + tid;
                wr[kk][0] = p[0];   wr[kk][1] = p[256];
                wr[kk][2] = p[512]; wr[kk][3] = p[768];
            }
            #pragma unroll
            for (int w = 0; w < BW; w++) {
                float4 hv = *reinterpret_cast<const float4*>(&h_s[w][k]);
                a0[w] = fmaf(wr[0][0], hv.x, a0[w]);
                a1[w] = fmaf(wr[0][1], hv.x, a1[w]);
                a2[w] = fmaf(wr[0][2], hv.x, a2[w]);
                a3[w] = fmaf(wr[0][3], hv.x, a3[w]);
                a0[w] = fmaf(wr[1][0], hv.y, a0[w]);
                a1[w] = fmaf(wr[1][1], hv.y, a1[w]);
                a2[w] = fmaf(wr[1][2], hv.y, a2[w]);
                a3[w] = fmaf(wr[1][3], hv.y, a3[w]);
                a0[w] = fmaf(wr[2][0], hv.z, a0[w]);
                a1[w] = fmaf(wr[2][1], hv.z, a1[w]);
                a2[w] = fmaf(wr[2][2], hv.z, a2[w]);
                a3[w] = fmaf(wr[2][3], hv.z, a3[w]);
                a0[w] = fmaf(wr[3][0], hv.w, a0[w]);
                a1[w] = fmaf(wr[3][1], hv.w, a1[w]);
                a2[w] = fmaf(wr[3][2], hv.w, a2[w]);
                a3[w] = fmaf(wr[3][3], hv.w, a3[w]);
            }
        }
        __syncthreads();   // all h reads done before rewriting h

        #pragma unroll
        for (int w = 0; w < BW; w++) {
            if (t < len_s[w]) {
                float gi = sigf(a0[w]);
                float gf = sigf(a1[w]);
                float gg = tanhf_(a2[w]);
                float go = sigf(a3[w]);
                c[w] = fmaf(gf, c[w], gi * gg);
                h_s[w][tid] = go * tanhf_(c[w]);
            }
        }
        __syncthreads();
    }

    // ---- epilogue: out = relu([word_emb ; h] @ W_lin.T + b_lin) ----
    float fa[BW];
    {
        float bj = blin[tid];
        #pragma unroll
        for (int w = 0; w < BW; w++) fa[w] = bj;
    }
    #pragma unroll 1
    for (int k = 0; k < 256; k += 4) {
        float wl[4];
        #pragma unroll
        for (int kk = 0; kk < 4; kk++) wl[kk] = d_WlinT[(k + kk) * WDIM + tid];
        #pragma unroll
        for (int w = 0; w < BW; w++) {
            float4 xv = *reinterpret_cast<const float4*>(&x_s[w][k]);
            fa[w] = fmaf(wl[0], xv.x, fa[w]);
            fa[w] = fmaf(wl[1], xv.y, fa[w]);
            fa[w] = fmaf(wl[2], xv.z, fa[w]);
            fa[w] = fmaf(wl[3], xv.w, fa[w]);
        }
    }
    #pragma unroll 1
    for (int k = 0; k < 256; k += 4) {
        float wl[4];
        #pragma unroll
        for (int kk = 0; kk < 4; kk++) wl[kk] = d_WlinT[(256 + k + kk) * WDIM + tid];
        #pragma unroll
        for (int w = 0; w < BW; w++) {
            float4 hv = *reinterpret_cast<const float4*>(&h_s[w][k]);
            fa[w] = fmaf(wl[0], hv.x, fa[w]);
            fa[w] = fmaf(wl[1], hv.y, fa[w]);
            fa[w] = fmaf(wl[2], hv.z, fa[w]);
            fa[w] = fmaf(wl[3], hv.w, fa[w]);
        }
    }
    #pragma unroll
    for (int w = 0; w < BW; w++)
        out[word_s[w] * WDIM + tid] = fmaxf(fa[w], 0.f);
}

extern "C" void kernel_launch(void* const* d_in, const int* in_sizes, int n_in,
                              void* d_out, int out_size) {
    const int*   chars = (const int*)d_in[0];
    const int*   lens  = (const int*)d_in[1];
    const float* wemb  = (const float*)d_in[2];
    const float* E     = (const float*)d_in[3];
    const float* Wih   = (const float*)d_in[4];
    const float* Whh   = (const float*)d_in[5];
    const float* bih   = (const float*)d_in[6];
    const float* bhh   = (const float*)d_in[7];
    const float* Wlin  = (const float*)d_in[8];
    const float* blin  = (const float*)d_in[9];
    float* out = (float*)d_out;

    k_zero<<<1, 32>>>();
    k_hist<<<NW / 256, 256>>>(lens);
    k_prepG<<<1024, 256>>>(E, Wih, bih, bhh);
    k_transWhh<<<256, 1024>>>(Whh);
    k_transWlin<<<128, 1024>>>(Wlin);
    k_scan<<<1, 1>>>();
    k_scatter<<<NW / 256, 256>>>(lens);
    k_lstm<<<NCTA, 256>>>(chars, lens, wemb, blin, out);
}